// round 12
// baseline (speedup 1.0000x reference)
#include <cuda_runtime.h>

// SinabsLIFModel fused: 3x (Linear + LIF) in ONE kernel.
// B=256, T=4096, widths 16->16->32->10.
//  - grid (32, 32): 8 batches x one 128-step chunk per block, 128-step warm-up
//    replay (alpha^128 ~ 1.7e-3 membrane error, ~6-sigma from any spike boundary).
//  - Per 32-step subchunk: stage x transposed -> pass1 (GEMM-ish h, f32x2 over
//    t-pairs, no horizontal adds) -> shfl exchange -> scan1 -> layer2 -> layer3
//    -> flush. s1/s2/outf live in per-batch smem unions; all inter-layer flow
//    stays inside one half-warp (syncwarp only, no global intermediates).
//  - Layers 2/3: per-subchunk all-zero input flags (ballot) -> fast path is
//    v *= alpha^32 + zero flush (exact: zero input + v<1 invariant => no spikes).

#define BATCH   256
#define TSTEPS  4096
#define TC      128
#define NCH     32
#define WARM    128
#define SUBT    32
#define NB      8
#define BSTRIDE 2848   /* bytes per batch union: x(2048) | s1(512)+s2(1024)+outf(1280) */

#define ALPHA   0.9512294245007140f    /* exp(-1/20)  */
#define ALPHA32 0.2018965179946554f    /* exp(-32/20) */

static __device__ __forceinline__ unsigned long long pk2(float lo, float hi) {
    unsigned long long r;
    asm("mov.b64 %0, {%1, %2};" : "=l"(r) : "f"(lo), "f"(hi));
    return r;
}
static __device__ __forceinline__ unsigned long long ffma2(unsigned long long a,
                                                           unsigned long long b,
                                                           unsigned long long c) {
    unsigned long long d;
    asm("fma.rn.f32x2 %0, %1, %2, %3;" : "=l"(d) : "l"(a), "l"(b), "l"(c));
    return d;
}
#define UNPK(lo, hi, u) asm("mov.b64 {%0,%1}, %2;" : "=f"(lo), "=f"(hi) : "l"(u))

__global__ void __launch_bounds__(128) k_fused(const float* __restrict__ x,
                                               const float* __restrict__ w1,
                                               const float* __restrict__ w2,
                                               const float* __restrict__ w3,
                                               float* __restrict__ out) {
    __shared__ __align__(16) unsigned char sh[NB * BSTRIDE];
    __shared__ int sh_f1[NB];
    __shared__ int sh_f2[NB];

    const int tid = threadIdx.x;
    const int b   = tid >> 4;        // 0..7 (batch within block)
    const int j   = tid & 15;        // neuron lane (scan1 j; layer2 pair-id; layer3 l)
    const int tg  = tid & 1;         // pass1 time-half
    const int j0  = tid & 14;        // pass1 neuron pair base
    const int b0g = blockIdx.x * NB;
    const int chunk = blockIdx.y;
    const int t0 = chunk * TC;
    const int warm = chunk ? WARM : 0;
    const int tstart = t0 - warm;
    const int nsub = (warm + TC) / SUBT;

    // layer-1 weights for this thread's 2 pass1 neurons, (1-alpha) folded in
    float wA[16], wB[16];
    const float onem = 1.0f - ALPHA;
#pragma unroll
    for (int c = 0; c < 16; c++) {
        wA[c] = onem * w1[j0 * 16 + c];
        wB[c] = onem * w1[(j0 + 1) * 16 + c];
    }

    float v1 = 0.0f, v2a = 0.0f, v2b = 0.0f, v3 = 0.0f;

    unsigned char* shb = sh + b * BSTRIDE;
    const float* xb = (const float*)shb;

    for (int sub = 0; sub < nsub; sub++) {
        const int ts = tstart + sub * SUBT;
        __syncthreads();   // protects prior-iteration smem (flush done) before restage

        {   // stage x TRANSPOSED: sh_x[r][c][t] (f32), conflict-free STS.32
            const float4* src = (const float4*)x;
#pragma unroll
            for (int i = 0; i < 8; i++) {
                int idx = tid + i * 128;          // 0..1023
                int r = idx >> 7;
                int i7 = idx & 127;
                int t = i7 & 31;
                int cg = i7 >> 5;                  // 0..3
                float4 v4 = src[((b0g + r) * TSTEPS + (ts + t)) * 4 + cg];
                float* d = (float*)(sh + r * BSTRIDE);
                d[(cg * 4 + 0) * 32 + t] = v4.x;
                d[(cg * 4 + 1) * 32 + t] = v4.y;
                d[(cg * 4 + 2) * 32 + t] = v4.z;
                d[(cg * 4 + 3) * 32 + t] = v4.w;
            }
        }
        __syncthreads();

        // ---- pass1: h for neurons (j0, j0+1) x 16 timesteps (half tg) ----
        unsigned long long hA[8], hB[8];
#pragma unroll
        for (int p = 0; p < 8; p++) { hA[p] = 0ull; hB[p] = 0ull; }
        {
            const float* xc = xb + tg * 16;
#pragma unroll
            for (int c = 0; c < 16; c++) {
                ulonglong2 q0 = *(const ulonglong2*)(xc + c * 32 + 0);
                ulonglong2 q1 = *(const ulonglong2*)(xc + c * 32 + 4);
                ulonglong2 q2 = *(const ulonglong2*)(xc + c * 32 + 8);
                ulonglong2 q3 = *(const ulonglong2*)(xc + c * 32 + 12);
                unsigned long long wa2 = pk2(wA[c], wA[c]);
                unsigned long long wb2 = pk2(wB[c], wB[c]);
                hA[0] = ffma2(q0.x, wa2, hA[0]);  hA[1] = ffma2(q0.y, wa2, hA[1]);
                hA[2] = ffma2(q1.x, wa2, hA[2]);  hA[3] = ffma2(q1.y, wa2, hA[3]);
                hA[4] = ffma2(q2.x, wa2, hA[4]);  hA[5] = ffma2(q2.y, wa2, hA[5]);
                hA[6] = ffma2(q3.x, wa2, hA[6]);  hA[7] = ffma2(q3.y, wa2, hA[7]);
                hB[0] = ffma2(q0.x, wb2, hB[0]);  hB[1] = ffma2(q0.y, wb2, hB[1]);
                hB[2] = ffma2(q1.x, wb2, hB[2]);  hB[3] = ffma2(q1.y, wb2, hB[3]);
                hB[4] = ffma2(q2.x, wb2, hB[4]);  hB[5] = ffma2(q2.y, wb2, hB[5]);
                hB[6] = ffma2(q3.x, wb2, hB[6]);  hB[7] = ffma2(q3.y, wb2, hB[7]);
            }
        }
        __syncwarp();
        // exchange halves with partner (tid^1): after this, thread owns j = j0+tg
        // with h0 = t 0..15, h1 = t 16..31.
        unsigned long long h0[8], h1[8];
#pragma unroll
        for (int p = 0; p < 8; p++) {
            unsigned long long send = tg ? hA[p] : hB[p];
            unsigned long long rec = __shfl_xor_sync(0xffffffffu, send, 1);
            h0[p] = tg ? rec : hA[p];
            h1[p] = tg ? hB[p] : rec;
        }

        // ---- scan1: LIF over 32 steps, s1[t][16] u8 at union offset 0 ----
        unsigned int orv = 0u;
        {
            unsigned char* s1p = shb + j;
            float vv = v1;
#pragma unroll
            for (int p = 0; p < 8; p++) {
                float f0, f1; UNPK(f0, f1, h0[p]);
                vv = fmaf(ALPHA, vv, f0);
                float s = fmaxf(floorf(vv), 0.0f); vv -= s;
                unsigned int si = (unsigned int)s; orv |= si;
                s1p[(2 * p) * 16] = (unsigned char)si;
                vv = fmaf(ALPHA, vv, f1);
                s = fmaxf(floorf(vv), 0.0f); vv -= s;
                si = (unsigned int)s; orv |= si;
                s1p[(2 * p + 1) * 16] = (unsigned char)si;
            }
#pragma unroll
            for (int p = 0; p < 8; p++) {
                float f0, f1; UNPK(f0, f1, h1[p]);
                vv = fmaf(ALPHA, vv, f0);
                float s = fmaxf(floorf(vv), 0.0f); vv -= s;
                unsigned int si = (unsigned int)s; orv |= si;
                s1p[(16 + 2 * p) * 16] = (unsigned char)si;
                vv = fmaf(ALPHA, vv, f1);
                s = fmaxf(floorf(vv), 0.0f); vv -= s;
                si = (unsigned int)s; orv |= si;
                s1p[(16 + 2 * p + 1) * 16] = (unsigned char)si;
            }
            v1 = vv;
        }
        __syncwarp();
        {
            unsigned bal = __ballot_sync(0xffffffffu, orv != 0u);
            int lane = tid & 31;
            if (lane == 0)  sh_f1[b] = (int)(bal & 0xFFFFu);
            if (lane == 16) sh_f1[b] = (int)(bal >> 16);
        }
        __syncwarp();

        // ---- layer2: neurons 2j, 2j+1; s2[t][32] u8 at union offset 512 ----
        unsigned int orv2 = 0u;
        if (sh_f1[b]) {
            float w2a[16], w2b[16];
#pragma unroll
            for (int c = 0; c < 16; c++) {
                w2a[c] = onem * w2[(2 * j) * 16 + c];
                w2b[c] = onem * w2[(2 * j + 1) * 16 + c];
            }
            const unsigned char* s1b = shb;
            unsigned char* s2b = shb + 512;
            for (int t = 0; t < SUBT; t++) {
                uint4 r = *(const uint4*)(s1b + t * 16);
                float ha = 0.0f, hb = 0.0f;
                if (r.x | r.y | r.z | r.w) {
                    unsigned int pq[4] = {r.x, r.y, r.z, r.w};
#pragma unroll
                    for (int q = 0; q < 4; q++) {
                        float f0 = (float)(pq[q] & 255u);
                        float f1 = (float)((pq[q] >> 8) & 255u);
                        float f2 = (float)((pq[q] >> 16) & 255u);
                        float f3 = (float)(pq[q] >> 24);
                        ha = fmaf(f0, w2a[q * 4 + 0], ha);
                        ha = fmaf(f1, w2a[q * 4 + 1], ha);
                        ha = fmaf(f2, w2a[q * 4 + 2], ha);
                        ha = fmaf(f3, w2a[q * 4 + 3], ha);
                        hb = fmaf(f0, w2b[q * 4 + 0], hb);
                        hb = fmaf(f1, w2b[q * 4 + 1], hb);
                        hb = fmaf(f2, w2b[q * 4 + 2], hb);
                        hb = fmaf(f3, w2b[q * 4 + 3], hb);
                    }
                }
                v2a = fmaf(ALPHA, v2a, ha);
                float sa = fmaxf(floorf(v2a), 0.0f); v2a -= sa;
                v2b = fmaf(ALPHA, v2b, hb);
                float sb = fmaxf(floorf(v2b), 0.0f); v2b -= sb;
                unsigned int sai = (unsigned int)sa, sbi = (unsigned int)sb;
                orv2 |= (sai | sbi);
                *(unsigned short*)(s2b + t * 32 + 2 * j) =
                    (unsigned short)(sai | (sbi << 8));
            }
        } else {
            v2a *= ALPHA32;
            v2b *= ALPHA32;
        }
        __syncwarp();
        {
            unsigned bal2 = __ballot_sync(0xffffffffu, orv2 != 0u);
            int lane = tid & 31;
            if (lane == 0)  sh_f2[b] = (int)(bal2 & 0xFFFFu);
            if (lane == 16) sh_f2[b] = (int)(bal2 >> 16);
        }
        __syncwarp();

        // ---- layer3: lanes j<10; outf[t][10] f32 at union offset 1536 ----
        if (sh_f2[b]) {
            if (j < 10) {
                float w3r[32];
#pragma unroll
                for (int c = 0; c < 32; c++) w3r[c] = onem * w3[j * 32 + c];
                const unsigned char* s2b = shb + 512;
                float* ofb = (float*)(shb + 1536);
                for (int t = 0; t < SUBT; t++) {
                    uint4 ra = *(const uint4*)(s2b + t * 32);
                    uint4 rb = *(const uint4*)(s2b + t * 32 + 16);
                    float h = 0.0f;
                    if (ra.x | ra.y | ra.z | ra.w | rb.x | rb.y | rb.z | rb.w) {
                        unsigned int pq[8] = {ra.x, ra.y, ra.z, ra.w,
                                              rb.x, rb.y, rb.z, rb.w};
#pragma unroll
                        for (int q = 0; q < 8; q++) {
                            h = fmaf((float)(pq[q] & 255u),         w3r[q * 4 + 0], h);
                            h = fmaf((float)((pq[q] >> 8) & 255u),  w3r[q * 4 + 1], h);
                            h = fmaf((float)((pq[q] >> 16) & 255u), w3r[q * 4 + 2], h);
                            h = fmaf((float)(pq[q] >> 24),          w3r[q * 4 + 3], h);
                        }
                    }
                    v3 = fmaf(ALPHA, v3, h);
                    float s = fmaxf(floorf(v3), 0.0f); v3 -= s;
                    ofb[t * 10 + j] = s;
                }
            }
        } else {
            v3 *= ALPHA32;
        }
        __syncwarp();

        // ---- flush (emit region only): warp w owns batches 2w, 2w+1 ----
        if (ts >= t0) {
            int w = tid >> 5, lane = tid & 31;
#pragma unroll
            for (int bs = 0; bs < 2; bs++) {
                int bb = 2 * w + bs;
                float* dst = out + ((b0g + bb) * TSTEPS + ts) * 10;  // 320 f contiguous
                if (sh_f2[bb] == 0) {
#pragma unroll
                    for (int k = 0; k < 10; k++) dst[lane + k * 32] = 0.0f;
                } else {
                    const float* sr = (const float*)(sh + bb * BSTRIDE + 1536);
#pragma unroll
                    for (int k = 0; k < 10; k++) dst[lane + k * 32] = sr[lane + k * 32];
                }
            }
        }
    }
}

extern "C" void kernel_launch(void* const* d_in, const int* in_sizes, int n_in,
                              void* d_out, int out_size) {
    const float* data = (const float*)d_in[0];   // [256,4096,16]
    const float* w1 = (const float*)d_in[1];     // [16,16]
    const float* w2 = (const float*)d_in[2];     // [32,16]
    const float* w3 = (const float*)d_in[3];     // [10,32]
    float* out = (float*)d_out;                  // [256,4096,10]

    k_fused<<<dim3(BATCH / NB, NCH), 128>>>(data, w1, w2, w3, out);
}

// round 13
// speedup vs baseline: 1.0037x; 1.0037x over previous
#include <cuda_runtime.h>

// SinabsLIFModel fused: 3x (Linear + LIF) in ONE kernel.
// B=256, T=4096, widths 16->16->32->10.
//  - grid (32, 32): 8 batches x one 128-step chunk per block, 128-step warm-up
//    replay (alpha^128 ~ 1.7e-3 membrane error, ~6-sigma from any spike boundary).
//  - Per 32-step subchunk: stage x transposed -> pass1 (GEMM-ish h, f32x2 over
//    t-pairs, no horizontal adds) -> shfl exchange -> scan1 -> layer2 -> layer3
//    -> flush. s1/s2/outf live in per-batch smem unions; all inter-layer flow
//    stays inside one half-warp (syncwarp only, no global intermediates).
//  - Layers 2/3: per-subchunk all-zero input flags (ballot) -> fast path is
//    v *= alpha^32 + zero flush (exact: zero input + v<1 invariant => no spikes).

#define BATCH   256
#define TSTEPS  4096
#define TC      128
#define NCH     32
#define WARM    128
#define SUBT    32
#define NB      8
#define BSTRIDE 2848   /* bytes per batch union: x(2048) | s1(512)+s2(1024)+outf(1280) */

#define ALPHA   0.9512294245007140f    /* exp(-1/20)  */
#define ALPHA32 0.2018965179946554f    /* exp(-32/20) */

static __device__ __forceinline__ unsigned long long pk2(float lo, float hi) {
    unsigned long long r;
    asm("mov.b64 %0, {%1, %2};" : "=l"(r) : "f"(lo), "f"(hi));
    return r;
}
static __device__ __forceinline__ unsigned long long ffma2(unsigned long long a,
                                                           unsigned long long b,
                                                           unsigned long long c) {
    unsigned long long d;
    asm("fma.rn.f32x2 %0, %1, %2, %3;" : "=l"(d) : "l"(a), "l"(b), "l"(c));
    return d;
}
#define UNPK(lo, hi, u) asm("mov.b64 {%0,%1}, %2;" : "=f"(lo), "=f"(hi) : "l"(u))

__global__ void __launch_bounds__(128) k_fused(const float* __restrict__ x,
                                               const float* __restrict__ w1,
                                               const float* __restrict__ w2,
                                               const float* __restrict__ w3,
                                               float* __restrict__ out) {
    __shared__ __align__(16) unsigned char sh[NB * BSTRIDE];
    __shared__ int sh_f1[NB];
    __shared__ int sh_f2[NB];

    const int tid = threadIdx.x;
    const int b   = tid >> 4;        // 0..7 (batch within block)
    const int j   = tid & 15;        // neuron lane (scan1 j; layer2 pair-id; layer3 l)
    const int tg  = tid & 1;         // pass1 time-half
    const int j0  = tid & 14;        // pass1 neuron pair base
    const int b0g = blockIdx.x * NB;
    const int chunk = blockIdx.y;
    const int t0 = chunk * TC;
    const int warm = chunk ? WARM : 0;
    const int tstart = t0 - warm;
    const int nsub = (warm + TC) / SUBT;

    // layer-1 weights for this thread's 2 pass1 neurons, (1-alpha) folded in
    float wA[16], wB[16];
    const float onem = 1.0f - ALPHA;
#pragma unroll
    for (int c = 0; c < 16; c++) {
        wA[c] = onem * w1[j0 * 16 + c];
        wB[c] = onem * w1[(j0 + 1) * 16 + c];
    }

    float v1 = 0.0f, v2a = 0.0f, v2b = 0.0f, v3 = 0.0f;

    unsigned char* shb = sh + b * BSTRIDE;
    const float* xb = (const float*)shb;

    for (int sub = 0; sub < nsub; sub++) {
        const int ts = tstart + sub * SUBT;
        __syncthreads();   // protects prior-iteration smem (flush done) before restage

        {   // stage x TRANSPOSED: sh_x[r][c][t] (f32), conflict-free STS.32
            const float4* src = (const float4*)x;
#pragma unroll
            for (int i = 0; i < 8; i++) {
                int idx = tid + i * 128;          // 0..1023
                int r = idx >> 7;
                int i7 = idx & 127;
                int t = i7 & 31;
                int cg = i7 >> 5;                  // 0..3
                float4 v4 = src[((b0g + r) * TSTEPS + (ts + t)) * 4 + cg];
                float* d = (float*)(sh + r * BSTRIDE);
                d[(cg * 4 + 0) * 32 + t] = v4.x;
                d[(cg * 4 + 1) * 32 + t] = v4.y;
                d[(cg * 4 + 2) * 32 + t] = v4.z;
                d[(cg * 4 + 3) * 32 + t] = v4.w;
            }
        }
        __syncthreads();

        // ---- pass1: h for neurons (j0, j0+1) x 16 timesteps (half tg) ----
        unsigned long long hA[8], hB[8];
#pragma unroll
        for (int p = 0; p < 8; p++) { hA[p] = 0ull; hB[p] = 0ull; }
        {
            const float* xc = xb + tg * 16;
#pragma unroll
            for (int c = 0; c < 16; c++) {
                ulonglong2 q0 = *(const ulonglong2*)(xc + c * 32 + 0);
                ulonglong2 q1 = *(const ulonglong2*)(xc + c * 32 + 4);
                ulonglong2 q2 = *(const ulonglong2*)(xc + c * 32 + 8);
                ulonglong2 q3 = *(const ulonglong2*)(xc + c * 32 + 12);
                unsigned long long wa2 = pk2(wA[c], wA[c]);
                unsigned long long wb2 = pk2(wB[c], wB[c]);
                hA[0] = ffma2(q0.x, wa2, hA[0]);  hA[1] = ffma2(q0.y, wa2, hA[1]);
                hA[2] = ffma2(q1.x, wa2, hA[2]);  hA[3] = ffma2(q1.y, wa2, hA[3]);
                hA[4] = ffma2(q2.x, wa2, hA[4]);  hA[5] = ffma2(q2.y, wa2, hA[5]);
                hA[6] = ffma2(q3.x, wa2, hA[6]);  hA[7] = ffma2(q3.y, wa2, hA[7]);
                hB[0] = ffma2(q0.x, wb2, hB[0]);  hB[1] = ffma2(q0.y, wb2, hB[1]);
                hB[2] = ffma2(q1.x, wb2, hB[2]);  hB[3] = ffma2(q1.y, wb2, hB[3]);
                hB[4] = ffma2(q2.x, wb2, hB[4]);  hB[5] = ffma2(q2.y, wb2, hB[5]);
                hB[6] = ffma2(q3.x, wb2, hB[6]);  hB[7] = ffma2(q3.y, wb2, hB[7]);
            }
        }
        __syncwarp();
        // exchange halves with partner (tid^1): after this, thread owns j = j0+tg
        // with h0 = t 0..15, h1 = t 16..31.
        unsigned long long h0[8], h1[8];
#pragma unroll
        for (int p = 0; p < 8; p++) {
            unsigned long long send = tg ? hA[p] : hB[p];
            unsigned long long rec = __shfl_xor_sync(0xffffffffu, send, 1);
            h0[p] = tg ? rec : hA[p];
            h1[p] = tg ? hB[p] : rec;
        }

        // ---- scan1: LIF over 32 steps, s1[t][16] u8 at union offset 0 ----
        unsigned int orv = 0u;
        {
            unsigned char* s1p = shb + j;
            float vv = v1;
#pragma unroll
            for (int p = 0; p < 8; p++) {
                float f0, f1; UNPK(f0, f1, h0[p]);
                vv = fmaf(ALPHA, vv, f0);
                float s = fmaxf(floorf(vv), 0.0f); vv -= s;
                unsigned int si = (unsigned int)s; orv |= si;
                s1p[(2 * p) * 16] = (unsigned char)si;
                vv = fmaf(ALPHA, vv, f1);
                s = fmaxf(floorf(vv), 0.0f); vv -= s;
                si = (unsigned int)s; orv |= si;
                s1p[(2 * p + 1) * 16] = (unsigned char)si;
            }
#pragma unroll
            for (int p = 0; p < 8; p++) {
                float f0, f1; UNPK(f0, f1, h1[p]);
                vv = fmaf(ALPHA, vv, f0);
                float s = fmaxf(floorf(vv), 0.0f); vv -= s;
                unsigned int si = (unsigned int)s; orv |= si;
                s1p[(16 + 2 * p) * 16] = (unsigned char)si;
                vv = fmaf(ALPHA, vv, f1);
                s = fmaxf(floorf(vv), 0.0f); vv -= s;
                si = (unsigned int)s; orv |= si;
                s1p[(16 + 2 * p + 1) * 16] = (unsigned char)si;
            }
            v1 = vv;
        }
        __syncwarp();
        {
            unsigned bal = __ballot_sync(0xffffffffu, orv != 0u);
            int lane = tid & 31;
            if (lane == 0)  sh_f1[b] = (int)(bal & 0xFFFFu);
            if (lane == 16) sh_f1[b] = (int)(bal >> 16);
        }
        __syncwarp();

        // ---- layer2: neurons 2j, 2j+1; s2[t][32] u8 at union offset 512 ----
        unsigned int orv2 = 0u;
        if (sh_f1[b]) {
            float w2a[16], w2b[16];
#pragma unroll
            for (int c = 0; c < 16; c++) {
                w2a[c] = onem * w2[(2 * j) * 16 + c];
                w2b[c] = onem * w2[(2 * j + 1) * 16 + c];
            }
            const unsigned char* s1b = shb;
            unsigned char* s2b = shb + 512;
            for (int t = 0; t < SUBT; t++) {
                uint4 r = *(const uint4*)(s1b + t * 16);
                float ha = 0.0f, hb = 0.0f;
                if (r.x | r.y | r.z | r.w) {
                    unsigned int pq[4] = {r.x, r.y, r.z, r.w};
#pragma unroll
                    for (int q = 0; q < 4; q++) {
                        float f0 = (float)(pq[q] & 255u);
                        float f1 = (float)((pq[q] >> 8) & 255u);
                        float f2 = (float)((pq[q] >> 16) & 255u);
                        float f3 = (float)(pq[q] >> 24);
                        ha = fmaf(f0, w2a[q * 4 + 0], ha);
                        ha = fmaf(f1, w2a[q * 4 + 1], ha);
                        ha = fmaf(f2, w2a[q * 4 + 2], ha);
                        ha = fmaf(f3, w2a[q * 4 + 3], ha);
                        hb = fmaf(f0, w2b[q * 4 + 0], hb);
                        hb = fmaf(f1, w2b[q * 4 + 1], hb);
                        hb = fmaf(f2, w2b[q * 4 + 2], hb);
                        hb = fmaf(f3, w2b[q * 4 + 3], hb);
                    }
                }
                v2a = fmaf(ALPHA, v2a, ha);
                float sa = fmaxf(floorf(v2a), 0.0f); v2a -= sa;
                v2b = fmaf(ALPHA, v2b, hb);
                float sb = fmaxf(floorf(v2b), 0.0f); v2b -= sb;
                unsigned int sai = (unsigned int)sa, sbi = (unsigned int)sb;
                orv2 |= (sai | sbi);
                *(unsigned short*)(s2b + t * 32 + 2 * j) =
                    (unsigned short)(sai | (sbi << 8));
            }
        } else {
            v2a *= ALPHA32;
            v2b *= ALPHA32;
        }
        __syncwarp();
        {
            unsigned bal2 = __ballot_sync(0xffffffffu, orv2 != 0u);
            int lane = tid & 31;
            if (lane == 0)  sh_f2[b] = (int)(bal2 & 0xFFFFu);
            if (lane == 16) sh_f2[b] = (int)(bal2 >> 16);
        }
        __syncwarp();

        // ---- layer3: lanes j<10; outf[t][10] f32 at union offset 1536 ----
        if (sh_f2[b]) {
            if (j < 10) {
                float w3r[32];
#pragma unroll
                for (int c = 0; c < 32; c++) w3r[c] = onem * w3[j * 32 + c];
                const unsigned char* s2b = shb + 512;
                float* ofb = (float*)(shb + 1536);
                for (int t = 0; t < SUBT; t++) {
                    uint4 ra = *(const uint4*)(s2b + t * 32);
                    uint4 rb = *(const uint4*)(s2b + t * 32 + 16);
                    float h = 0.0f;
                    if (ra.x | ra.y | ra.z | ra.w | rb.x | rb.y | rb.z | rb.w) {
                        unsigned int pq[8] = {ra.x, ra.y, ra.z, ra.w,
                                              rb.x, rb.y, rb.z, rb.w};
#pragma unroll
                        for (int q = 0; q < 8; q++) {
                            h = fmaf((float)(pq[q] & 255u),         w3r[q * 4 + 0], h);
                            h = fmaf((float)((pq[q] >> 8) & 255u),  w3r[q * 4 + 1], h);
                            h = fmaf((float)((pq[q] >> 16) & 255u), w3r[q * 4 + 2], h);
                            h = fmaf((float)(pq[q] >> 24),          w3r[q * 4 + 3], h);
                        }
                    }
                    v3 = fmaf(ALPHA, v3, h);
                    float s = fmaxf(floorf(v3), 0.0f); v3 -= s;
                    ofb[t * 10 + j] = s;
                }
            }
        } else {
            v3 *= ALPHA32;
        }
        __syncwarp();

        // ---- flush (emit region only): warp w owns batches 2w, 2w+1 ----
        if (ts >= t0) {
            int w = tid >> 5, lane = tid & 31;
#pragma unroll
            for (int bs = 0; bs < 2; bs++) {
                int bb = 2 * w + bs;
                float* dst = out + ((b0g + bb) * TSTEPS + ts) * 10;  // 320 f contiguous
                if (sh_f2[bb] == 0) {
#pragma unroll
                    for (int k = 0; k < 10; k++) dst[lane + k * 32] = 0.0f;
                } else {
                    const float* sr = (const float*)(sh + bb * BSTRIDE + 1536);
#pragma unroll
                    for (int k = 0; k < 10; k++) dst[lane + k * 32] = sr[lane + k * 32];
                }
            }
        }
    }
}

extern "C" void kernel_launch(void* const* d_in, const int* in_sizes, int n_in,
                              void* d_out, int out_size) {
    const float* data = (const float*)d_in[0];   // [256,4096,16]
    const float* w1 = (const float*)d_in[1];     // [16,16]
    const float* w2 = (const float*)d_in[2];     // [32,16]
    const float* w3 = (const float*)d_in[3];     // [10,32]
    float* out = (float*)d_out;                  // [256,4096,10]

    k_fused<<<dim3(BATCH / NB, NCH), 128>>>(data, w1, w2, w3, out);
}